// round 5
// baseline (speedup 1.0000x reference)
#include <cuda_runtime.h>
#include <cstdint>

// Problem constants (B=32, H=W=56, C=384, heads=12, ws=7, shift=3)
#define HEADS   12
#define WS      7
#define NTOK    49
#define NWIN    2048
#define M_TOTAL (NWIN * NTOK)   // 100352
#define N_QKV   1152
#define N_PROJ  384
#define KDIM    384

// GEMM tiling: CTA 128x128, 256 threads (8 warps, warp tile 64x32),
// BK=32 (12 K-steps, half the barriers), 3-stage cp.async ring.
#define BM 128
#define BN 128
#define BK 32
#define KSTEPS (KDIM / BK)        // 12
#define APAD 36                   // smem row stride (floats): conflict-free frags
#define STAGE_FLOATS (BM * APAD)  // 4608
#define AB_STAGE (2 * STAGE_FLOATS)
#define NSTG 3
#define SMEM_BYTES (NSTG * AB_STAGE * 4)   // 110592

// Scratch (__device__ globals: sanctioned allocation-free path)
__device__ float g_qkv[(size_t)M_TOTAL * N_QKV];
__device__ float g_attn[(size_t)M_TOTAL * N_PROJ];
__device__ float g_xr  [(size_t)M_TOTAL * KDIM];
__device__ float g_wtq [(size_t)N_QKV * KDIM];
__device__ float g_wtp [(size_t)N_PROJ * KDIM];

// ---------------------------------------------------------------------------
// roll+window gather map (shift is involution-symmetric): m = win*49 + t
__device__ __forceinline__ int win_src_index(int m) {
    int win = m / NTOK, t = m - win * NTOK;
    int b  = win >> 6, wi = win & 63;
    int wh = wi >> 3,  ww = wi & 7;
    int r  = t / WS,   c  = t - r * WS;
    int row = wh * WS + r + 3; if (row >= 56) row -= 56;
    int col = ww * WS + c + 3; if (col >= 56) col -= 56;
    return b * 3136 + row * 56 + col;
}

__device__ __forceinline__ uint32_t smem_u32(const void* p) {
    uint32_t a;
    asm("{ .reg .u64 t; cvta.to.shared.u64 t, %1; cvt.u32.u64 %0, t; }" : "=r"(a) : "l"(p));
    return a;
}
__device__ __forceinline__ float round_tf32(float v) {
    uint32_t r;
    asm("cvt.rna.tf32.f32 %0, %1;" : "=r"(r) : "f"(v));
    return __uint_as_float(r);
}

#define CP16(dst, src) \
    asm volatile("cp.async.cg.shared.global [%0], [%1], 16;" :: "r"(dst), "l"(src) : "memory")
#define CP_COMMIT() asm volatile("cp.async.commit_group;" ::: "memory")
#define CP_WAIT1()  asm volatile("cp.async.wait_group 1;" ::: "memory")
#define CP_WAIT0()  asm volatile("cp.async.wait_group 0;" ::: "memory")

#define MMA_TF32(c, a, b) \
    asm volatile("mma.sync.aligned.m16n8k8.row.col.f32.tf32.tf32.f32 " \
        "{%0,%1,%2,%3}, {%4,%5,%6,%7}, {%8,%9}, {%0,%1,%2,%3};" \
        : "+f"((c)[0]), "+f"((c)[1]), "+f"((c)[2]), "+f"((c)[3]) \
        : "r"((a)[0]), "r"((a)[1]), "r"((a)[2]), "r"((a)[3]), "r"((b)[0]), "r"((b)[1]))

// ---------------------------------------------------------------------------
// tf32 mma.sync GEMM. GATHER fuses roll/window into A rows, SCATTER into C rows.
template <int N_TOTAL, bool GATHER, bool SCATTER>
__global__ void __launch_bounds__(256, 2)
gemm_mma(const float* __restrict__ A, const float* __restrict__ WT,
         const float* __restrict__ bias, float* __restrict__ C)
{
    extern __shared__ float sm[];
    const uint32_t smb = smem_u32(sm);

    const int tid  = threadIdx.x;
    const int wid  = tid >> 5, lane = tid & 31;
    const int g    = lane >> 2, t = lane & 3;
    const int wm   = wid & 1, wn = wid >> 1;       // warp grid 2(M) x 4(N)
    const int m0   = blockIdx.y * BM, n0 = blockIdx.x * BN;

    // loads: 2 threads per row, 16 floats (64B = 4x CP16) each
    const int lrow = tid >> 1, lseg = (tid & 1) * 16;
    const float* arow = A + (size_t)(GATHER ? win_src_index(m0 + lrow) : (m0 + lrow)) * KDIM + lseg;
    const float* brow = WT + (size_t)(n0 + lrow) * KDIM + lseg;
    const uint32_t a_dst = smb + ((uint32_t)lrow * APAD + lseg) * 4;
    const uint32_t b_dst = a_dst + STAGE_FLOATS * 4;

    auto load_stage = [&](int s, int kt) {
        const uint32_t so = (uint32_t)s * AB_STAGE * 4;
        const float* ap = arow + kt * BK;
        const float* bp = brow + kt * BK;
#pragma unroll
        for (int q = 0; q < 4; q++) {
            CP16(a_dst + so + q * 16, ap + q * 4);
            CP16(b_dst + so + q * 16, bp + q * 4);
        }
    };

    float c[4][4][4];
#pragma unroll
    for (int i = 0; i < 4; i++)
#pragma unroll
        for (int j = 0; j < 4; j++)
#pragma unroll
            for (int q = 0; q < 4; q++) c[i][j][q] = 0.f;

    // prologue: fill NSTG-1 = 2 stages
    load_stage(0, 0); CP_COMMIT();
    load_stage(1, 1); CP_COMMIT();

    int sidx = 0;                    // kt % 3
    for (int kt = 0; kt < KSTEPS; kt++) {
        if (kt < KSTEPS - 1) CP_WAIT1(); else CP_WAIT0();
        __syncthreads();

        // prefetch into the slot consumed last iteration (safe past the barrier)
        if (kt + 2 < KSTEPS) {
            int ps = sidx - 1; if (ps < 0) ps += NSTG;   // (kt+2) % 3 == (kt-1) % 3
            load_stage(ps, kt + 2); CP_COMMIT();
        }

        const uint32_t* AsU = (const uint32_t*)(sm + sidx * AB_STAGE);
        const uint32_t* BsU = AsU + STAGE_FLOATS;
        if (++sidx == NSTG) sidx = 0;

#pragma unroll
        for (int ks = 0; ks < 4; ks++) {
            const int ko = ks * 8;
            uint32_t a[4][4];
#pragma unroll
            for (int i = 0; i < 4; i++) {
                const int r0 = (wm * 64 + i * 16 + g) * APAD + ko + t;
                a[i][0] = AsU[r0];
                a[i][1] = AsU[r0 + 8 * APAD];
                a[i][2] = AsU[r0 + 4];
                a[i][3] = AsU[r0 + 8 * APAD + 4];
            }
            uint32_t b[4][2];
#pragma unroll
            for (int j = 0; j < 4; j++) {
                const int nb = (wn * 32 + j * 8 + g) * APAD + ko + t;
                b[j][0] = BsU[nb];
                b[j][1] = BsU[nb + 4];
            }
#pragma unroll
            for (int i = 0; i < 4; i++)
#pragma unroll
                for (int j = 0; j < 4; j++) MMA_TF32(c[i][j], a[i], b[j]);
        }
    }

    // reg-direct epilogue: each 4-lane group stores 32B contiguous (1 sector)
    const int ncolb = n0 + wn * 32;
    float2 bj[4];
#pragma unroll
    for (int j = 0; j < 4; j++)
        bj[j] = *reinterpret_cast<const float2*>(&bias[ncolb + j * 8 + 2 * t]);

#pragma unroll
    for (int i = 0; i < 4; i++) {
        const int mrow = m0 + wm * 64 + i * 16 + g;
        const size_t r0 = SCATTER ? (size_t)win_src_index(mrow)     : (size_t)mrow;
        const size_t r1 = SCATTER ? (size_t)win_src_index(mrow + 8) : (size_t)(mrow + 8);
        float* p0 = C + r0 * N_TOTAL + ncolb + 2 * t;
        float* p1 = C + r1 * N_TOTAL + ncolb + 2 * t;
#pragma unroll
        for (int j = 0; j < 4; j++) {
            *reinterpret_cast<float2*>(p0 + j * 8) =
                make_float2(c[i][j][0] + bj[j].x, c[i][j][1] + bj[j].y);
            *reinterpret_cast<float2*>(p1 + j * 8) =
                make_float2(c[i][j][2] + bj[j].x, c[i][j][3] + bj[j].y);
        }
    }
}

// ---------------------------------------------------------------------------
// Preprocessing: transpose W[K][N] -> WT[N][K], rounded to tf32 (rna, unbiased)
__global__ void transpose_round(const float* __restrict__ W, float* __restrict__ WT,
                                int K, int N)
{
    __shared__ float tbuf[32][33];
    const int n0 = blockIdx.x * 32, k0 = blockIdx.y * 32;
    const int tx = threadIdx.x, ty = threadIdx.y;   // 32 x 8
#pragma unroll
    for (int i = 0; i < 4; i++)
        tbuf[ty + 8 * i][tx] = W[(size_t)(k0 + ty + 8 * i) * N + n0 + tx];
    __syncthreads();
#pragma unroll
    for (int i = 0; i < 4; i++)
        WT[(size_t)(n0 + ty + 8 * i) * K + k0 + tx] = round_tf32(tbuf[tx][ty + 8 * i]);
}

__global__ void round_x_kernel(const float4* __restrict__ in, float4* __restrict__ out, int n4)
{
    int i = blockIdx.x * blockDim.x + threadIdx.x;
    if (i < n4) {
        float4 v = in[i];
        v.x = round_tf32(v.x); v.y = round_tf32(v.y);
        v.z = round_tf32(v.z); v.w = round_tf32(v.w);
        out[i] = v;
    }
}

// ---------------------------------------------------------------------------
// Per-(window, head) attention: 49x32 Q,K,V -> softmax(QK^T*scale + bias) V
__global__ void __launch_bounds__(64)
attn_kernel(const float* __restrict__ bias_table)
{
    const int blk  = blockIdx.x;
    const int head = blk % HEADS;
    const int win  = blk / HEADS;

    __shared__ float Qs[NTOK * 36];
    __shared__ float Ks[NTOK * 32];
    __shared__ float Vs[NTOK * 32];
    __shared__ float Os[NTOK * 36];
    __shared__ float Ss[NTOK * 50];

    const int tid = threadIdx.x;
    const float* base = g_qkv + (size_t)win * NTOK * N_QKV + head * 32;

    for (int idx = tid; idx < NTOK * 8; idx += 64) {
        int tt = idx >> 3, w = idx & 7;
        const float4* p = reinterpret_cast<const float4*>(base + (size_t)tt * N_QKV) + w;
        reinterpret_cast<float4*>(Qs)[tt * 9 + w] = p[0];
        reinterpret_cast<float4*>(Ks)[tt * 8 + w] = p[96];    // +384 floats
        reinterpret_cast<float4*>(Vs)[tt * 8 + w] = p[192];   // +768 floats
    }
    __syncthreads();

    if (tid < NTOK) {
        const int i  = tid;
        const int ri = i / WS, ci = i - ri * WS;
        const float scale = 0.17677669529663687f;

        float4 q[8];
        const float4* Q4 = reinterpret_cast<const float4*>(Qs);
        const float4* K4 = reinterpret_cast<const float4*>(Ks);
        const float4* V4 = reinterpret_cast<const float4*>(Vs);
#pragma unroll
        for (int w = 0; w < 8; w++) q[w] = Q4[i * 9 + w];

        float mx = -1e30f;
        for (int j = 0; j < NTOK; j++) {
            float acc = 0.f;
#pragma unroll
            for (int w = 0; w < 8; w++) {
                float4 k = K4[j * 8 + w];
                acc += q[w].x * k.x + q[w].y * k.y + q[w].z * k.z + q[w].w * k.w;
            }
            int rj = j / WS, cj = j - rj * WS;
            int rel = (ri - rj + 6) * 13 + (ci - cj + 6);
            acc = acc * scale + __ldg(&bias_table[rel * HEADS + head]);
            Ss[i * 50 + j] = acc;
            mx = fmaxf(mx, acc);
        }
        float sum = 0.f;
        for (int j = 0; j < NTOK; j++) {
            float p = __expf(Ss[i * 50 + j] - mx);
            Ss[i * 50 + j] = p;
            sum += p;
        }
        const float inv = 1.0f / sum;

        float4 o[8];
#pragma unroll
        for (int w = 0; w < 8; w++) o[w] = make_float4(0.f, 0.f, 0.f, 0.f);
        for (int j = 0; j < NTOK; j++) {
            float p = Ss[i * 50 + j] * inv;
#pragma unroll
            for (int w = 0; w < 8; w++) {
                float4 v = V4[j * 8 + w];
                o[w].x += p * v.x; o[w].y += p * v.y;
                o[w].z += p * v.z; o[w].w += p * v.w;
            }
        }
        float4* O4 = reinterpret_cast<float4*>(Os);
#pragma unroll
        for (int w = 0; w < 8; w++) {
            float4 v = o[w];
            v.x = round_tf32(v.x); v.y = round_tf32(v.y);
            v.z = round_tf32(v.z); v.w = round_tf32(v.w);
            O4[i * 9 + w] = v;
        }
    }
    __syncthreads();

    float* outbase = g_attn + (size_t)win * NTOK * N_PROJ + head * 32;
    for (int idx = tid; idx < NTOK * 8; idx += 64) {
        int tt = idx >> 3, w = idx & 7;
        reinterpret_cast<float4*>(outbase + (size_t)tt * N_PROJ)[w] =
            reinterpret_cast<const float4*>(Os)[tt * 9 + w];
    }
}

// ---------------------------------------------------------------------------
extern "C" void kernel_launch(void* const* d_in, const int* in_sizes, int n_in,
                              void* d_out, int out_size)
{
    const float* x          = (const float*)d_in[0];
    const float* qkv_w      = (const float*)d_in[1];
    const float* qkv_b      = (const float*)d_in[2];
    const float* proj_w     = (const float*)d_in[3];
    const float* proj_b     = (const float*)d_in[4];
    const float* bias_table = (const float*)d_in[5];
    float* out = (float*)d_out;

    float *qkv_p, *attn_p, *xr_p, *wtq_p, *wtp_p;
    cudaGetSymbolAddress((void**)&qkv_p,  g_qkv);
    cudaGetSymbolAddress((void**)&attn_p, g_attn);
    cudaGetSymbolAddress((void**)&xr_p,   g_xr);
    cudaGetSymbolAddress((void**)&wtq_p,  g_wtq);
    cudaGetSymbolAddress((void**)&wtp_p,  g_wtp);

    cudaFuncSetAttribute(gemm_mma<N_QKV, true, false>,
                         cudaFuncAttributeMaxDynamicSharedMemorySize, SMEM_BYTES);
    cudaFuncSetAttribute(gemm_mma<N_PROJ, false, true>,
                         cudaFuncAttributeMaxDynamicSharedMemorySize, SMEM_BYTES);

    // 0) preprocessing (tf32 rna rounding; weights transposed to K-major)
    {
        int n4 = M_TOTAL * KDIM / 4;
        round_x_kernel<<<(n4 + 255) / 256, 256>>>((const float4*)x, (float4*)xr_p, n4);
        transpose_round<<<dim3(N_QKV / 32, KDIM / 32), dim3(32, 8)>>>(qkv_w, wtq_p, KDIM, N_QKV);
        transpose_round<<<dim3(N_PROJ / 32, KDIM / 32), dim3(32, 8)>>>(proj_w, wtp_p, KDIM, N_PROJ);
    }
    // 1) QKV GEMM (tf32 mma.sync, fused window/roll gather)
    gemm_mma<N_QKV, true, false><<<dim3(N_QKV / BN, M_TOTAL / BM), 256, SMEM_BYTES>>>(
        xr_p, wtq_p, qkv_b, qkv_p);
    // 2) window attention
    attn_kernel<<<NWIN * HEADS, 64>>>(bias_table);
    // 3) proj GEMM (tf32 mma.sync, fused inverse roll/window scatter)
    gemm_mma<N_PROJ, false, true><<<dim3(N_PROJ / BN, M_TOTAL / BM), 256, SMEM_BYTES>>>(
        attn_p, wtp_p, proj_b, out);
}

// round 6
// speedup vs baseline: 1.1686x; 1.1686x over previous
#include <cuda_runtime.h>
#include <cstdint>

// Problem constants (B=32, H=W=56, C=384, heads=12, ws=7, shift=3)
#define HEADS   12
#define WS      7
#define NTOK    49
#define NWIN    2048
#define M_TOTAL (NWIN * NTOK)   // 100352
#define N_QKV   1152
#define N_PROJ  384
#define KDIM    384

// GEMM tiling: CTA 128x128, 256 threads (8 warps, warp tile 64x32),
// BK=16, 4-stage cp.async ring (R4 shape), LDS.64 paired fragments.
// K values inside every 8-float group are stored permuted [0,4,1,5,2,6,3,7]
// in g_xr / WT / g_attn so each mma fragment pair (k=t, k=t+4) is contiguous.
#define BM 128
#define BN 128
#define BK 16
#define KSTEPS (KDIM / BK)        // 24
#define APAD 24                   // row stride (floats): LDS.64 conflict-free
#define STAGE_FLOATS (BM * APAD)  // 3072
#define AB_STAGE (2 * STAGE_FLOATS)
#define NSTG 4
#define SMEM_BYTES (NSTG * AB_STAGE * 4)   // 98304

// Scratch (__device__ globals: sanctioned allocation-free path)
__device__ float g_qkv[(size_t)M_TOTAL * N_QKV];
__device__ float g_attn[(size_t)M_TOTAL * N_PROJ];
__device__ float g_xr  [(size_t)M_TOTAL * KDIM];
__device__ float g_wtq [(size_t)N_QKV * KDIM];
__device__ float g_wtp [(size_t)N_PROJ * KDIM];

// ---------------------------------------------------------------------------
// roll+window gather map (shift is involution-symmetric): m = win*49 + t
__device__ __forceinline__ int win_src_index(int m) {
    int win = m / NTOK, t = m - win * NTOK;
    int b  = win >> 6, wi = win & 63;
    int wh = wi >> 3,  ww = wi & 7;
    int r  = t / WS,   c  = t - r * WS;
    int row = wh * WS + r + 3; if (row >= 56) row -= 56;
    int col = ww * WS + c + 3; if (col >= 56) col -= 56;
    return b * 3136 + row * 56 + col;
}

__device__ __forceinline__ uint32_t smem_u32(const void* p) {
    uint32_t a;
    asm("{ .reg .u64 t; cvta.to.shared.u64 t, %1; cvt.u32.u64 %0, t; }" : "=r"(a) : "l"(p));
    return a;
}
__device__ __forceinline__ float round_tf32(float v) {
    uint32_t r;
    asm("cvt.rna.tf32.f32 %0, %1;" : "=r"(r) : "f"(v));
    return __uint_as_float(r);
}

#define CP16(dst, src) \
    asm volatile("cp.async.cg.shared.global [%0], [%1], 16;" :: "r"(dst), "l"(src) : "memory")
#define CP_COMMIT() asm volatile("cp.async.commit_group;" ::: "memory")
#define CP_WAIT2()  asm volatile("cp.async.wait_group 2;" ::: "memory")
#define CP_WAIT1()  asm volatile("cp.async.wait_group 1;" ::: "memory")
#define CP_WAIT0()  asm volatile("cp.async.wait_group 0;" ::: "memory")

#define MMA_TF32(c, a, b) \
    asm volatile("mma.sync.aligned.m16n8k8.row.col.f32.tf32.tf32.f32 " \
        "{%0,%1,%2,%3}, {%4,%5,%6,%7}, {%8,%9}, {%0,%1,%2,%3};" \
        : "+f"((c)[0]), "+f"((c)[1]), "+f"((c)[2]), "+f"((c)[3]) \
        : "r"((a)[0]), "r"((a)[1]), "r"((a)[2]), "r"((a)[3]), "r"((b)[0]), "r"((b)[1]))

// ---------------------------------------------------------------------------
// tf32 mma.sync GEMM. GATHER fuses roll/window into A rows, SCATTER into C rows.
// A and WT rows are k-pair-permuted (see top comment).
template <int N_TOTAL, bool GATHER, bool SCATTER>
__global__ void __launch_bounds__(256, 2)
gemm_mma(const float* __restrict__ A, const float* __restrict__ WT,
         const float* __restrict__ bias, float* __restrict__ C)
{
    extern __shared__ float sm[];
    const uint32_t smb = smem_u32(sm);

    const int tid  = threadIdx.x;
    const int wid  = tid >> 5, lane = tid & 31;
    const int g    = lane >> 2, t = lane & 3;
    const int wm   = wid & 1, wn = wid >> 1;       // warp grid 2(M) x 4(N)
    const int m0   = blockIdx.y * BM, n0 = blockIdx.x * BN;

    // loads: 2 threads per row, 8 floats (32B = 2x CP16) each
    const int lrow = tid >> 1, lseg = (tid & 1) * 8;
    const float* arow = A + (size_t)(GATHER ? win_src_index(m0 + lrow) : (m0 + lrow)) * KDIM + lseg;
    const float* brow = WT + (size_t)(n0 + lrow) * KDIM + lseg;
    const uint32_t a_dst = smb + ((uint32_t)lrow * APAD + lseg) * 4;
    const uint32_t b_dst = a_dst + STAGE_FLOATS * 4;

    auto load_stage = [&](int s, int kt) {
        const uint32_t so = (uint32_t)s * AB_STAGE * 4;
        const float* ap = arow + kt * BK;
        const float* bp = brow + kt * BK;
        CP16(a_dst + so,      ap);
        CP16(a_dst + so + 16, ap + 4);
        CP16(b_dst + so,      bp);
        CP16(b_dst + so + 16, bp + 4);
    };

    float c[4][4][4];
#pragma unroll
    for (int i = 0; i < 4; i++)
#pragma unroll
        for (int j = 0; j < 4; j++)
#pragma unroll
            for (int q = 0; q < 4; q++) c[i][j][q] = 0.f;

    // prologue: fill NSTG-1 stages
#pragma unroll
    for (int s = 0; s < NSTG - 1; s++) { load_stage(s, s); CP_COMMIT(); }

#pragma unroll 4
    for (int kt = 0; kt < KSTEPS; kt++) {
        const int rem = KSTEPS - 1 - kt;
        if (rem >= 2)      CP_WAIT2();
        else if (rem == 1) CP_WAIT1();
        else               CP_WAIT0();
        __syncthreads();

        // prefetch into the slot consumed last iteration (safe past the barrier)
        if (kt + NSTG - 1 < KSTEPS) { load_stage((kt + NSTG - 1) & 3, kt + NSTG - 1); CP_COMMIT(); }

        const uint2* AsU2 = (const uint2*)(sm + (kt & 3) * AB_STAGE);
        const uint2* BsU2 = AsU2 + STAGE_FLOATS / 2;

#pragma unroll
        for (int ks = 0; ks < 2; ks++) {
            const int ko4 = ks * 4;        // uint2 offset within row (8 floats)
            uint32_t a[4][4];
#pragma unroll
            for (int i = 0; i < 4; i++) {
                const int r2 = (wm * 64 + i * 16 + g) * (APAD / 2) + ko4 + t;
                uint2 p0 = AsU2[r2];                     // (k=t, k=t+4) row g
                uint2 p1 = AsU2[r2 + 8 * (APAD / 2)];    // row g+8
                a[i][0] = p0.x; a[i][1] = p1.x; a[i][2] = p0.y; a[i][3] = p1.y;
            }
            uint32_t b[4][2];
#pragma unroll
            for (int j = 0; j < 4; j++) {
                const int n2 = (wn * 32 + j * 8 + g) * (APAD / 2) + ko4 + t;
                uint2 q = BsU2[n2];
                b[j][0] = q.x; b[j][1] = q.y;
            }
#pragma unroll
            for (int i = 0; i < 4; i++)
#pragma unroll
                for (int j = 0; j < 4; j++) MMA_TF32(c[i][j], a[i], b[j]);
        }
    }

    // reg-direct epilogue: each 4-lane group stores 32B contiguous (1 sector)
    const int ncolb = n0 + wn * 32;
    float2 bj[4];
#pragma unroll
    for (int j = 0; j < 4; j++)
        bj[j] = *reinterpret_cast<const float2*>(&bias[ncolb + j * 8 + 2 * t]);

#pragma unroll
    for (int i = 0; i < 4; i++) {
        const int mrow = m0 + wm * 64 + i * 16 + g;
        const size_t r0 = SCATTER ? (size_t)win_src_index(mrow)     : (size_t)mrow;
        const size_t r1 = SCATTER ? (size_t)win_src_index(mrow + 8) : (size_t)(mrow + 8);
        float* p0 = C + r0 * N_TOTAL + ncolb + 2 * t;
        float* p1 = C + r1 * N_TOTAL + ncolb + 2 * t;
#pragma unroll
        for (int j = 0; j < 4; j++) {
            *reinterpret_cast<float2*>(p0 + j * 8) =
                make_float2(c[i][j][0] + bj[j].x, c[i][j][1] + bj[j].y);
            *reinterpret_cast<float2*>(p1 + j * 8) =
                make_float2(c[i][j][2] + bj[j].x, c[i][j][3] + bj[j].y);
        }
    }
}

// ---------------------------------------------------------------------------
// Preprocessing: transpose W[K][N] -> WT[N][Kperm], rounded to tf32 (rna)
__global__ void transpose_round(const float* __restrict__ W, float* __restrict__ WT,
                                int K, int N)
{
    __shared__ float tbuf[32][33];
    const int n0 = blockIdx.x * 32, k0 = blockIdx.y * 32;
    const int tx = threadIdx.x, ty = threadIdx.y;   // 32 x 8
#pragma unroll
    for (int i = 0; i < 4; i++)
        tbuf[ty + 8 * i][tx] = W[(size_t)(k0 + ty + 8 * i) * N + n0 + tx];
    __syncthreads();
    // permute k within each 8-group: k -> (k&~7) | 2*(k&3) | ((k>>2)&1)
    const int kpos = (tx & ~7) | ((tx & 3) * 2) | ((tx >> 2) & 1);
#pragma unroll
    for (int i = 0; i < 4; i++)
        WT[(size_t)(n0 + ty + 8 * i) * K + k0 + kpos] = round_tf32(tbuf[tx][ty + 8 * i]);
}

// x -> tf32-rounded, k-pair-permuted copy (per 8-float group)
__global__ void round_x_perm(const float4* __restrict__ in, float4* __restrict__ out, int n8)
{
    int i = blockIdx.x * blockDim.x + threadIdx.x;
    if (i < n8) {
        float4 v0 = in[2 * i], v1 = in[2 * i + 1];
        v0.x = round_tf32(v0.x); v0.y = round_tf32(v0.y);
        v0.z = round_tf32(v0.z); v0.w = round_tf32(v0.w);
        v1.x = round_tf32(v1.x); v1.y = round_tf32(v1.y);
        v1.z = round_tf32(v1.z); v1.w = round_tf32(v1.w);
        out[2 * i]     = make_float4(v0.x, v1.x, v0.y, v1.y);   // k0,k4,k1,k5
        out[2 * i + 1] = make_float4(v0.z, v1.z, v0.w, v1.w);   // k2,k6,k3,k7
    }
}

// ---------------------------------------------------------------------------
// Per-(window, head) attention: 49x32 Q,K,V -> softmax(QK^T*scale + bias) V
// Bias slice staged in smem; output written tf32-rounded + k-pair-permuted.
__global__ void __launch_bounds__(64)
attn_kernel(const float* __restrict__ bias_table)
{
    const int blk  = blockIdx.x;
    const int head = blk % HEADS;
    const int win  = blk / HEADS;

    __shared__ float Qs[NTOK * 36];
    __shared__ float Ks[NTOK * 32];
    __shared__ float Vs[NTOK * 32];
    __shared__ float Os[NTOK * 36];
    __shared__ float Ss[NTOK * 50];
    __shared__ float Bb[169];

    const int tid = threadIdx.x;
    const float* base = g_qkv + (size_t)win * NTOK * N_QKV + head * 32;

    for (int idx = tid; idx < 169; idx += 64)
        Bb[idx] = __ldg(&bias_table[idx * HEADS + head]);
    for (int idx = tid; idx < NTOK * 8; idx += 64) {
        int tt = idx >> 3, w = idx & 7;
        const float4* p = reinterpret_cast<const float4*>(base + (size_t)tt * N_QKV) + w;
        reinterpret_cast<float4*>(Qs)[tt * 9 + w] = p[0];
        reinterpret_cast<float4*>(Ks)[tt * 8 + w] = p[96];    // +384 floats
        reinterpret_cast<float4*>(Vs)[tt * 8 + w] = p[192];   // +768 floats
    }
    __syncthreads();

    if (tid < NTOK) {
        const int i  = tid;
        const int ri = i / WS, ci = i - ri * WS;
        const float scale = 0.17677669529663687f;

        float4 q[8];
        const float4* Q4 = reinterpret_cast<const float4*>(Qs);
        const float4* K4 = reinterpret_cast<const float4*>(Ks);
        const float4* V4 = reinterpret_cast<const float4*>(Vs);
#pragma unroll
        for (int w = 0; w < 8; w++) q[w] = Q4[i * 9 + w];

        float mx = -1e30f;
        for (int j = 0; j < NTOK; j++) {
            float acc = 0.f;
#pragma unroll
            for (int w = 0; w < 8; w++) {
                float4 k = K4[j * 8 + w];
                acc += q[w].x * k.x + q[w].y * k.y + q[w].z * k.z + q[w].w * k.w;
            }
            int rj = j / WS, cj = j - rj * WS;
            int rel = (ri - rj + 6) * 13 + (ci - cj + 6);
            acc = acc * scale + Bb[rel];
            Ss[i * 50 + j] = acc;
            mx = fmaxf(mx, acc);
        }
        float sum = 0.f;
        for (int j = 0; j < NTOK; j++) {
            float p = __expf(Ss[i * 50 + j] - mx);
            Ss[i * 50 + j] = p;
            sum += p;
        }
        const float inv = 1.0f / sum;

        float4 o[8];
#pragma unroll
        for (int w = 0; w < 8; w++) o[w] = make_float4(0.f, 0.f, 0.f, 0.f);
        for (int j = 0; j < NTOK; j++) {
            float p = Ss[i * 50 + j] * inv;
#pragma unroll
            for (int w = 0; w < 8; w++) {
                float4 v = V4[j * 8 + w];
                o[w].x += p * v.x; o[w].y += p * v.y;
                o[w].z += p * v.z; o[w].w += p * v.w;
            }
        }
        // round + k-pair permute per 8-dim group for the proj GEMM
        float4* O4 = reinterpret_cast<float4*>(Os);
#pragma unroll
        for (int g2 = 0; g2 < 4; g2++) {
            float4 e = o[2 * g2], f = o[2 * g2 + 1];
            e.x = round_tf32(e.x); e.y = round_tf32(e.y);
            e.z = round_tf32(e.z); e.w = round_tf32(e.w);
            f.x = round_tf32(f.x); f.y = round_tf32(f.y);
            f.z = round_tf32(f.z); f.w = round_tf32(f.w);
            O4[i * 9 + 2 * g2]     = make_float4(e.x, f.x, e.y, f.y);
            O4[i * 9 + 2 * g2 + 1] = make_float4(e.z, f.z, e.w, f.w);
        }
    }
    __syncthreads();

    float* outbase = g_attn + (size_t)win * NTOK * N_PROJ + head * 32;
    for (int idx = tid; idx < NTOK * 8; idx += 64) {
        int tt = idx >> 3, w = idx & 7;
        reinterpret_cast<float4*>(outbase + (size_t)tt * N_PROJ)[w] =
            reinterpret_cast<const float4*>(Os)[tt * 9 + w];
    }
}

// ---------------------------------------------------------------------------
extern "C" void kernel_launch(void* const* d_in, const int* in_sizes, int n_in,
                              void* d_out, int out_size)
{
    const float* x          = (const float*)d_in[0];
    const float* qkv_w      = (const float*)d_in[1];
    const float* qkv_b      = (const float*)d_in[2];
    const float* proj_w     = (const float*)d_in[3];
    const float* proj_b     = (const float*)d_in[4];
    const float* bias_table = (const float*)d_in[5];
    float* out = (float*)d_out;

    float *qkv_p, *attn_p, *xr_p, *wtq_p, *wtp_p;
    cudaGetSymbolAddress((void**)&qkv_p,  g_qkv);
    cudaGetSymbolAddress((void**)&attn_p, g_attn);
    cudaGetSymbolAddress((void**)&xr_p,   g_xr);
    cudaGetSymbolAddress((void**)&wtq_p,  g_wtq);
    cudaGetSymbolAddress((void**)&wtp_p,  g_wtp);

    cudaFuncSetAttribute(gemm_mma<N_QKV, true, false>,
                         cudaFuncAttributeMaxDynamicSharedMemorySize, SMEM_BYTES);
    cudaFuncSetAttribute(gemm_mma<N_PROJ, false, true>,
                         cudaFuncAttributeMaxDynamicSharedMemorySize, SMEM_BYTES);

    // 0) preprocessing (tf32 rna rounding; k-pair permutation; weights -> K-major)
    {
        int n8 = M_TOTAL * KDIM / 8;
        round_x_perm<<<(n8 + 255) / 256, 256>>>((const float4*)x, (float4*)xr_p, n8);
        transpose_round<<<dim3(N_QKV / 32, KDIM / 32), dim3(32, 8)>>>(qkv_w, wtq_p, KDIM, N_QKV);
        transpose_round<<<dim3(N_PROJ / 32, KDIM / 32), dim3(32, 8)>>>(proj_w, wtp_p, KDIM, N_PROJ);
    }
    // 1) QKV GEMM (tf32 mma.sync, fused window/roll gather)
    gemm_mma<N_QKV, true, false><<<dim3(N_QKV / BN, M_TOTAL / BM), 256, SMEM_BYTES>>>(
        xr_p, wtq_p, qkv_b, qkv_p);
    // 2) window attention
    attn_kernel<<<NWIN * HEADS, 64>>>(bias_table);
    // 3) proj GEMM (tf32 mma.sync, fused inverse roll/window scatter)
    gemm_mma<N_PROJ, false, true><<<dim3(N_PROJ / BN, M_TOTAL / BM), 256, SMEM_BYTES>>>(
        attn_p, wtp_p, proj_b, out);
}